// round 3
// baseline (speedup 1.0000x reference)
#include <cuda_runtime.h>

#define B_ 256
#define T_ 1024
#define K_ 128

__device__ float g_logz[B_];
__device__ float g_gold[B_];

__device__ __forceinline__ void fma2(unsigned long long &acc, unsigned long long a, unsigned long long b) {
    asm("fma.rn.f32x2 %0, %1, %2, %0;" : "+l"(acc) : "l"(a), "l"(b));
}
__device__ __forceinline__ unsigned long long add2(unsigned long long a, unsigned long long b) {
    unsigned long long c;
    asm("add.rn.f32x2 %0, %1, %2;" : "=l"(c) : "l"(a), "l"(b));
    return c;
}
__device__ __forceinline__ unsigned long long pack2(float x, float y) {
    unsigned long long r;
    asm("mov.b64 %0, {%1, %2};" : "=l"(r) : "f"(x), "f"(y));
    return r;
}
__device__ __forceinline__ float2 unpack2(unsigned long long v) {
    float2 f;
    asm("mov.b64 {%0, %1}, %2;" : "=f"(f.x), "=f"(f.y) : "l"(v));
    return f;
}
__device__ __forceinline__ float warp_max(float v) {
    #pragma unroll
    for (int o = 16; o > 0; o >>= 1) v = fmaxf(v, __shfl_xor_sync(0xffffffffu, v, o));
    return v;
}
__device__ __forceinline__ float warp_sum(float v) {
    #pragma unroll
    for (int o = 16; o > 0; o >>= 1) v += __shfl_xor_sync(0xffffffffu, v, o);
    return v;
}

// Forward logZ: TWO batches per CTA of 128 threads, interleaved in-thread.
// Thread j owns output state j for both chains. E column j (exp(trans[:,j]))
// lives in registers (64 packed f32x2) and is SHARED by both chains.
// p = exp(alpha) per chain in smem, double-buffered; one barrier per step.
__global__ __launch_bounds__(128, 1) void crf_fwd(
    const float* __restrict__ emis,   // (B,T,K)
    const int* __restrict__ mask,     // (B,T) int32
    const float* __restrict__ start,  // (K)
    const float* __restrict__ endv,   // (K)
    const float* __restrict__ trans)  // (K,K)
{
    const int b0 = blockIdx.x * 2;
    const int j = threadIdx.x;
    __shared__ __align__(16) float pA[2][K_];
    __shared__ __align__(16) float pB[2][K_];
    __shared__ float wrA[4], wrB[4];

    // E[:,j] as packed pairs over i
    unsigned long long e2[K_ / 2];
    #pragma unroll
    for (int k = 0; k < K_ / 2; ++k) {
        float ea = __expf(trans[(2 * k) * K_ + j]);
        float eb = __expf(trans[(2 * k + 1) * K_ + j]);
        e2[k] = pack2(ea, eb);
    }

    const float* __restrict__ ebA = emis + (size_t)b0 * T_ * K_;
    const float* __restrict__ ebB = ebA + (size_t)T_ * K_;
    const int* __restrict__ mbA = mask + (size_t)b0 * T_;
    const int* __restrict__ mbB = mbA + T_;

    float st = start[j];
    float alA = st + ebA[j];
    float alB = st + ebB[j];
    float CA = 0.0f, CB = 0.0f;

    // prefetch 2 steps ahead
    float emA_a = ebA[1 * K_ + j], emA_b = ebA[2 * K_ + j];
    float emB_a = ebB[1 * K_ + j], emB_b = ebB[2 * K_ + j];
    int mkA_a = mbA[1], mkA_b = mbA[2];
    int mkB_a = mbB[1], mkB_b = mbB[2];

    for (int t = 1; t < T_; ++t) {
        float emA = emA_a; emA_a = emA_b;
        float emB = emB_a; emB_a = emB_b;
        int mkA = mkA_a; mkA_a = mkA_b;
        int mkB = mkB_a; mkB_a = mkB_b;

        pA[t & 1][j] = __expf(alA);
        pB[t & 1][j] = __expf(alB);
        __syncthreads();

        if (t + 2 < T_) {
            emA_b = ebA[(size_t)(t + 2) * K_ + j];
            emB_b = ebB[(size_t)(t + 2) * K_ + j];
            mkA_b = mbA[t + 2];
            mkB_b = mbB[t + 2];
        }

        const ulonglong2* __restrict__ pvA = (const ulonglong2*)pA[t & 1];
        const ulonglong2* __restrict__ pvB = (const ulonglong2*)pB[t & 1];
        unsigned long long aA0 = 0ull, aA1 = 0ull, aA2 = 0ull, aA3 = 0ull;
        unsigned long long aB0 = 0ull, aB1 = 0ull, aB2 = 0ull, aB3 = 0ull;
        #pragma unroll
        for (int k = 0; k < 32; k += 2) {
            ulonglong2 qA0 = pvA[k];
            ulonglong2 qA1 = pvA[k + 1];
            ulonglong2 qB0 = pvB[k];
            ulonglong2 qB1 = pvB[k + 1];
            fma2(aA0, qA0.x, e2[2 * k]);
            fma2(aA1, qA0.y, e2[2 * k + 1]);
            fma2(aA2, qA1.x, e2[2 * k + 2]);
            fma2(aA3, qA1.y, e2[2 * k + 3]);
            fma2(aB0, qB0.x, e2[2 * k]);
            fma2(aB1, qB0.y, e2[2 * k + 1]);
            fma2(aB2, qB1.x, e2[2 * k + 2]);
            fma2(aB3, qB1.y, e2[2 * k + 3]);
        }
        aA0 = add2(aA0, aA1); aA2 = add2(aA2, aA3); aA0 = add2(aA0, aA2);
        aB0 = add2(aB0, aB1); aB2 = add2(aB2, aB3); aB0 = add2(aB0, aB2);
        float2 spA = unpack2(aA0);
        float2 spB = unpack2(aB0);
        float sA = spA.x + spA.y;
        float sB = spB.x + spB.y;

        float anA = __logf(sA) + emA;
        float anB = __logf(sB) + emB;
        alA = mkA ? anA : alA;
        alB = mkB ? anB : alB;

        // periodic renormalization (both chains, one barrier)
        if ((t & 3) == 0) {
            float mA = warp_max(alA);
            float mB = warp_max(alB);
            if ((j & 31) == 0) { wrA[j >> 5] = mA; wrB[j >> 5] = mB; }
            __syncthreads();
            mA = fmaxf(fmaxf(wrA[0], wrA[1]), fmaxf(wrA[2], wrA[3]));
            mB = fmaxf(fmaxf(wrB[0], wrB[1]), fmaxf(wrB[2], wrB[3]));
            alA -= mA; CA += mA;
            alB -= mB; CB += mB;
        }
    }

    // logZ = C + logsumexp_j(alpha_j + end_j), both chains
    float ev = endv[j];
    float vA = alA + ev;
    float vB = alB + ev;
    float mA = warp_max(vA);
    float mB = warp_max(vB);
    if ((j & 31) == 0) { wrA[j >> 5] = mA; wrB[j >> 5] = mB; }
    __syncthreads();
    mA = fmaxf(fmaxf(wrA[0], wrA[1]), fmaxf(wrA[2], wrA[3]));
    mB = fmaxf(fmaxf(wrB[0], wrB[1]), fmaxf(wrB[2], wrB[3]));
    float eA = __expf(vA - mA);
    float eB = __expf(vB - mB);
    float wsA = warp_sum(eA);
    float wsB = warp_sum(eB);
    __syncthreads();
    if ((j & 31) == 0) { wrA[j >> 5] = wsA; wrB[j >> 5] = wsB; }
    __syncthreads();
    if (j == 0) {
        float sA = (wrA[0] + wrA[1]) + (wrA[2] + wrA[3]);
        float sB = (wrB[0] + wrB[1]) + (wrB[2] + wrB[3]);
        g_logz[b0]     = CA + mA + __logf(sA);
        g_logz[b0 + 1] = CB + mB + __logf(sB);
    }
}

// Gold path score: one batch per CTA of 128 threads, strided over t.
__global__ void crf_gold(
    const float* __restrict__ emis,
    const int* __restrict__ tags,
    const int* __restrict__ mask,
    const float* __restrict__ start,
    const float* __restrict__ endv,
    const float* __restrict__ trans)
{
    const int b = blockIdx.x;
    const int tid = threadIdx.x;
    const float* __restrict__ eb = emis + (size_t)b * T_ * K_;
    const int* __restrict__ tg = tags + (size_t)b * T_;
    const int* __restrict__ mb = mask + (size_t)b * T_;

    float sc = 0.0f;
    int cnt = 0;
    for (int t = tid; t < T_; t += 128) {
        int mt = mb[t];
        cnt += mt ? 1 : 0;
        if (t >= 1 && mt && mb[t - 1]) {
            int pr = tg[t - 1]; pr = pr < 0 ? 0 : pr;
            int cr = tg[t];     cr = cr < 0 ? 0 : cr;
            sc += trans[pr * K_ + cr] + eb[(size_t)t * K_ + cr];
        }
    }

    __shared__ float wsc[4];
    __shared__ int wcn[4];
    float s = warp_sum(sc);
    int c = cnt;
    #pragma unroll
    for (int o = 16; o > 0; o >>= 1) c += __shfl_xor_sync(0xffffffffu, c, o);
    if ((tid & 31) == 0) { wsc[tid >> 5] = s; wcn[tid >> 5] = c; }
    __syncthreads();
    if (tid == 0) {
        float total = (wsc[0] + wsc[1]) + (wsc[2] + wsc[3]);
        int ctot = wcn[0] + wcn[1] + wcn[2] + wcn[3];
        int t0 = tg[0];
        float sc0 = (start[t0] + eb[t0]) * (mb[0] ? 1.0f : 0.0f);
        int lenm1 = ctot - 1;
        int last = tg[lenm1];
        g_gold[b] = total + sc0 + endv[last];
    }
}

// Final: mean over batches of (logZ - gold), fixed-order tree reduction.
__global__ void crf_finish(float* __restrict__ out) {
    __shared__ float sm[B_];
    int i = threadIdx.x;
    sm[i] = g_logz[i] - g_gold[i];
    __syncthreads();
    #pragma unroll
    for (int s = 128; s > 0; s >>= 1) {
        if (i < s) sm[i] += sm[i + s];
        __syncthreads();
    }
    if (i == 0) out[0] = sm[0] * (1.0f / B_);
}

extern "C" void kernel_launch(void* const* d_in, const int* in_sizes, int n_in,
                              void* d_out, int out_size) {
    const float* emis   = (const float*)d_in[0];
    const int* tags     = (const int*)d_in[1];
    const int* mask     = (const int*)d_in[2];
    const float* start  = (const float*)d_in[3];
    const float* endv   = (const float*)d_in[4];
    const float* trans  = (const float*)d_in[5];
    float* out = (float*)d_out;

    crf_fwd<<<B_ / 2, K_>>>(emis, mask, start, endv, trans);
    crf_gold<<<B_, K_>>>(emis, tags, mask, start, endv, trans);
    crf_finish<<<1, B_>>>(out);
}

// round 4
// speedup vs baseline: 1.1137x; 1.1137x over previous
#include <cuda_runtime.h>

#define B_ 256
#define T_ 1024
#define K_ 128

// padded p-layout: states 0..63 at [0,64), states 64..127 at [68,132)
// (the +4 float gap de-conflicts banks between the two half-readers)
#define PSTRIDE 136

__device__ float g_logz[B_];
__device__ float g_gold[B_];

__device__ __forceinline__ void fma2(unsigned long long &acc, unsigned long long a, unsigned long long b) {
    asm("fma.rn.f32x2 %0, %1, %2, %0;" : "+l"(acc) : "l"(a), "l"(b));
}
__device__ __forceinline__ unsigned long long add2(unsigned long long a, unsigned long long b) {
    unsigned long long c;
    asm("add.rn.f32x2 %0, %1, %2;" : "=l"(c) : "l"(a), "l"(b));
    return c;
}
__device__ __forceinline__ unsigned long long pack2(float x, float y) {
    unsigned long long r;
    asm("mov.b64 %0, {%1, %2};" : "=l"(r) : "f"(x), "f"(y));
    return r;
}
__device__ __forceinline__ float2 unpack2(unsigned long long v) {
    float2 f;
    asm("mov.b64 {%0, %1}, %2;" : "=f"(f.x), "=f"(f.y) : "l"(v));
    return f;
}
__device__ __forceinline__ float warp_max(float v) {
    #pragma unroll
    for (int o = 16; o > 0; o >>= 1) v = fmaxf(v, __shfl_xor_sync(0xffffffffu, v, o));
    return v;
}
__device__ __forceinline__ float warp_sum(float v) {
    #pragma unroll
    for (int o = 16; o > 0; o >>= 1) v += __shfl_xor_sync(0xffffffffu, v, o);
    return v;
}

// Forward logZ in the EXP DOMAIN: p_t = (p_{t-1} @ E) * exp(em_t), masked.
// One batch per CTA of 256 threads. Lane pair (2j, 2j+1) owns state j:
// even half-thread accumulates i=0..63, odd i=64..127, combined by shfl_xor(1).
// E half-column lives in 32 packed f32x2 registers per thread.
// No exp/log on the recurrence critical path; exp(em) comes from the prefetch.
__global__ __launch_bounds__(256, 2) void crf_fwd(
    const float* __restrict__ emis,   // (B,T,K)
    const int* __restrict__ mask,     // (B,T) int32
    const float* __restrict__ start,  // (K)
    const float* __restrict__ endv,   // (K)
    const float* __restrict__ trans)  // (K,K)
{
    const int b = blockIdx.x;
    const int tid = threadIdx.x;
    const int j = tid >> 1;       // state 0..127
    const int h = tid & 1;        // which i-half this thread accumulates
    const int slot = j + ((j >> 6) << 2);  // padded p position for state j

    __shared__ __align__(16) float pbuf[2][PSTRIDE];
    __shared__ float wred[8];

    // E[i, j] for i in [h*64, h*64+64), packed over i-pairs
    unsigned long long e2[32];
    #pragma unroll
    for (int k = 0; k < 32; ++k) {
        int i0 = h * 64 + 2 * k;
        float ea = __expf(trans[i0 * K_ + j]);
        float eb = __expf(trans[(i0 + 1) * K_ + j]);
        e2[k] = pack2(ea, eb);
    }

    const float* __restrict__ eb = emis + (size_t)b * T_ * K_;
    const int* __restrict__ mb = mask + (size_t)b * T_;

    // t = 0
    float p = __expf(start[j] + eb[j]);
    float C = 0.0f;
    if (h == 0) pbuf[0][slot] = p;

    // prefetch 2 steps ahead; exp(em) computed off the critical chain
    float eem_a = __expf(eb[1 * K_ + j]);
    float eem_b = __expf(eb[2 * K_ + j]);
    int mk_a = mb[1];
    int mk_b = mb[2];
    __syncthreads();

    for (int t = 1; t < T_; ++t) {
        const int rd = (t + 1) & 1;  // buffer written at t-1
        const int wr = t & 1;

        float eem = eem_a; eem_a = eem_b;
        int mk = mk_a; mk_a = mk_b;

        // half-GEMV: s = sum over my 64 i's of p_i * E[i][j]
        const ulonglong2* __restrict__ pv =
            (const ulonglong2*)(pbuf[rd] + h * 68);
        unsigned long long a0 = 0ull, a1 = 0ull, a2 = 0ull, a3 = 0ull;
        #pragma unroll
        for (int k = 0; k < 16; k += 2) {
            ulonglong2 q0 = pv[k];
            ulonglong2 q1 = pv[k + 1];
            fma2(a0, q0.x, e2[2 * k]);
            fma2(a1, q0.y, e2[2 * k + 1]);
            fma2(a2, q1.x, e2[2 * k + 2]);
            fma2(a3, q1.y, e2[2 * k + 3]);
        }
        a0 = add2(a0, a1);
        a2 = add2(a2, a3);
        a0 = add2(a0, a2);
        float2 sp = unpack2(a0);
        float s = sp.x + sp.y;
        s += __shfl_xor_sync(0xffffffffu, s, 1);  // combine halves

        p = mk ? s * eem : p;

        // prefetch t+2 (off critical path)
        if (t + 2 < T_) {
            eem_b = __expf(eb[(size_t)(t + 2) * K_ + j]);
            mk_b = mb[t + 2];
        }

        // periodic renormalization: divide by CTA max, accumulate log
        if ((t & 3) == 0) {
            float m = warp_max(p);
            if ((tid & 31) == 0) wred[tid >> 5] = m;
            __syncthreads();
            m = fmaxf(fmaxf(fmaxf(wred[0], wred[1]), fmaxf(wred[2], wred[3])),
                      fmaxf(fmaxf(wred[4], wred[5]), fmaxf(wred[6], wred[7])));
            p *= __frcp_rn(m);
            C += __logf(m);
        }

        if (h == 0) pbuf[wr][slot] = p;
        __syncthreads();
    }

    // logZ = C + log(sum_j p_j * exp(end_j)); even lanes contribute
    float v = (h == 0) ? p * __expf(endv[j]) : 0.0f;
    float ws = warp_sum(v);
    if ((tid & 31) == 0) wred[tid >> 5] = ws;
    __syncthreads();
    if (tid == 0) {
        float sm = ((wred[0] + wred[1]) + (wred[2] + wred[3]))
                 + ((wred[4] + wred[5]) + (wred[6] + wred[7]));
        g_logz[b] = C + __logf(sm);
    }
}

// Gold path score: one batch per CTA of 128 threads, strided over t.
__global__ void crf_gold(
    const float* __restrict__ emis,
    const int* __restrict__ tags,
    const int* __restrict__ mask,
    const float* __restrict__ start,
    const float* __restrict__ endv,
    const float* __restrict__ trans)
{
    const int b = blockIdx.x;
    const int tid = threadIdx.x;
    const float* __restrict__ eb = emis + (size_t)b * T_ * K_;
    const int* __restrict__ tg = tags + (size_t)b * T_;
    const int* __restrict__ mb = mask + (size_t)b * T_;

    float sc = 0.0f;
    int cnt = 0;
    for (int t = tid; t < T_; t += 128) {
        int mt = mb[t];
        cnt += mt ? 1 : 0;
        if (t >= 1 && mt && mb[t - 1]) {
            int pr = tg[t - 1]; pr = pr < 0 ? 0 : pr;
            int cr = tg[t];     cr = cr < 0 ? 0 : cr;
            sc += trans[pr * K_ + cr] + eb[(size_t)t * K_ + cr];
        }
    }

    __shared__ float wsc[4];
    __shared__ int wcn[4];
    float s = warp_sum(sc);
    int c = cnt;
    #pragma unroll
    for (int o = 16; o > 0; o >>= 1) c += __shfl_xor_sync(0xffffffffu, c, o);
    if ((tid & 31) == 0) { wsc[tid >> 5] = s; wcn[tid >> 5] = c; }
    __syncthreads();
    if (tid == 0) {
        float total = (wsc[0] + wsc[1]) + (wsc[2] + wsc[3]);
        int ctot = wcn[0] + wcn[1] + wcn[2] + wcn[3];
        int t0 = tg[0];
        float sc0 = (start[t0] + eb[t0]) * (mb[0] ? 1.0f : 0.0f);
        int lenm1 = ctot - 1;
        int last = tg[lenm1];
        g_gold[b] = total + sc0 + endv[last];
    }
}

// Final: mean over batches of (logZ - gold), fixed-order tree reduction.
__global__ void crf_finish(float* __restrict__ out) {
    __shared__ float sm[B_];
    int i = threadIdx.x;
    sm[i] = g_logz[i] - g_gold[i];
    __syncthreads();
    #pragma unroll
    for (int s = 128; s > 0; s >>= 1) {
        if (i < s) sm[i] += sm[i + s];
        __syncthreads();
    }
    if (i == 0) out[0] = sm[0] * (1.0f / B_);
}

extern "C" void kernel_launch(void* const* d_in, const int* in_sizes, int n_in,
                              void* d_out, int out_size) {
    const float* emis   = (const float*)d_in[0];
    const int* tags     = (const int*)d_in[1];
    const int* mask     = (const int*)d_in[2];
    const float* start  = (const float*)d_in[3];
    const float* endv   = (const float*)d_in[4];
    const float* trans  = (const float*)d_in[5];
    float* out = (float*)d_out;

    crf_fwd<<<B_, 256>>>(emis, mask, start, endv, trans);
    crf_gold<<<B_, 128>>>(emis, tags, mask, start, endv, trans);
    crf_finish<<<1, B_>>>(out);
}

// round 5
// speedup vs baseline: 1.2616x; 1.1328x over previous
#include <cuda_runtime.h>

#define B_ 256
#define T_ 1024
#define K_ 128
#define LN2 0.6931471805599453f
#define SHIFT 12

__device__ float g_logz[B_];
__device__ float g_gold[B_];

__device__ __forceinline__ void fma2(unsigned long long &acc, unsigned long long a, unsigned long long b) {
    asm("fma.rn.f32x2 %0, %1, %2, %0;" : "+l"(acc) : "l"(a), "l"(b));
}
__device__ __forceinline__ unsigned long long add2(unsigned long long a, unsigned long long b) {
    unsigned long long c;
    asm("add.rn.f32x2 %0, %1, %2;" : "=l"(c) : "l"(a), "l"(b));
    return c;
}
__device__ __forceinline__ unsigned long long pack2(float x, float y) {
    unsigned long long r;
    asm("mov.b64 %0, {%1, %2};" : "=l"(r) : "f"(x), "f"(y));
    return r;
}
__device__ __forceinline__ float2 unpack2(unsigned long long v) {
    float2 f;
    asm("mov.b64 {%0, %1}, %2;" : "=f"(f.x), "=f"(f.y) : "l"(v));
    return f;
}
__device__ __forceinline__ float warp_max(float v) {
    #pragma unroll
    for (int o = 16; o > 0; o >>= 1) v = fmaxf(v, __shfl_xor_sync(0xffffffffu, v, o));
    return v;
}
__device__ __forceinline__ float warp_sum(float v) {
    #pragma unroll
    for (int o = 16; o > 0; o >>= 1) v += __shfl_xor_sync(0xffffffffu, v, o);
    return v;
}

// Forward logZ, exp domain: p_t = (p_{t-1} @ E) * exp(em_t) * 2^-SHIFT  (masked).
// One batch per CTA of 128 threads; thread j owns state j.
// E column j in 64 packed f32x2 regs. p broadcast via smem, double-buffered.
// No MUFU on the recursion chain; exp(em)*2^-SHIFT comes from a 3-deep prefetch.
// Exact power-of-2 renorm every 16 steps (integer exponent bookkeeping).
__global__ __launch_bounds__(128, 2) void crf_fwd(
    const float* __restrict__ emis,   // (B,T,K)
    const int* __restrict__ mask,     // (B,T) int32
    const float* __restrict__ start,  // (K)
    const float* __restrict__ endv,   // (K)
    const float* __restrict__ trans)  // (K,K)
{
    const int b = blockIdx.x;
    const int j = threadIdx.x;
    __shared__ __align__(16) float pbuf[2][K_];
    __shared__ float wred[4];

    // E[:,j] packed over i-pairs
    unsigned long long e2[K_ / 2];
    #pragma unroll
    for (int k = 0; k < K_ / 2; ++k) {
        float ea = __expf(trans[(2 * k) * K_ + j]);
        float eb = __expf(trans[(2 * k + 1) * K_ + j]);
        e2[k] = pack2(ea, eb);
    }

    const float* __restrict__ eb = emis + (size_t)b * T_ * K_;
    const int* __restrict__ mb = mask + (size_t)b * T_;

    const float sc12 = __int_as_float((127 - SHIFT) << 23);  // 2^-SHIFT exact

    float p = __expf(start[j] + eb[j]);  // t = 0
    int kacc = 0;   // accumulated renorm exponent (exact)
    int cnt = 0;    // masked update count (each contributes 2^-SHIFT)
    pbuf[0][j] = p;

    // 3-deep prefetch of exp(em)*2^-SHIFT and mask
    float eA = __expf(eb[1 * K_ + j]) * sc12;
    float eB = __expf(eb[2 * K_ + j]) * sc12;
    float eC = __expf(eb[3 * K_ + j]) * sc12;
    int mA = mb[1], mB = mb[2], mC = mb[3];
    __syncthreads();

    for (int t = 1; t < T_; ++t) {
        const int rd = (t + 1) & 1;
        const int wr = t & 1;

        float eem = eA; eA = eB; eB = eC;
        int mk = mA; mA = mB; mB = mC;
        if (t + 3 < T_) {
            eC = __expf(eb[(size_t)(t + 3) * K_ + j]) * sc12;
            mC = mb[t + 3];
        }

        // s_j = sum_i p_i * E[i][j], 8 independent FFMA2 chains of depth 8
        const ulonglong2* __restrict__ pv = (const ulonglong2*)pbuf[rd];
        unsigned long long a0 = 0ull, a1 = 0ull, a2 = 0ull, a3 = 0ull;
        unsigned long long a4 = 0ull, a5 = 0ull, a6 = 0ull, a7 = 0ull;
        #pragma unroll
        for (int k = 0; k < 8; ++k) {
            ulonglong2 q0 = pv[4 * k];
            ulonglong2 q1 = pv[4 * k + 1];
            ulonglong2 q2 = pv[4 * k + 2];
            ulonglong2 q3 = pv[4 * k + 3];
            fma2(a0, q0.x, e2[8 * k]);
            fma2(a1, q0.y, e2[8 * k + 1]);
            fma2(a2, q1.x, e2[8 * k + 2]);
            fma2(a3, q1.y, e2[8 * k + 3]);
            fma2(a4, q2.x, e2[8 * k + 4]);
            fma2(a5, q2.y, e2[8 * k + 5]);
            fma2(a6, q3.x, e2[8 * k + 6]);
            fma2(a7, q3.y, e2[8 * k + 7]);
        }
        a0 = add2(a0, a1); a2 = add2(a2, a3);
        a4 = add2(a4, a5); a6 = add2(a6, a7);
        a0 = add2(a0, a2); a4 = add2(a4, a6);
        a0 = add2(a0, a4);
        float2 sp = unpack2(a0);
        float s = sp.x + sp.y;

        p = mk ? s * eem : p;
        cnt += mk ? 1 : 0;

        // exact power-of-2 renorm every 16 steps
        if ((t & 15) == 0) {
            float m = warp_max(p);
            if ((j & 31) == 0) wred[j >> 5] = m;
            __syncthreads();
            m = fmaxf(fmaxf(wred[0], wred[1]), fmaxf(wred[2], wred[3]));
            int ke = __float2int_rd(__log2f(m));
            p *= __int_as_float((127 - ke) << 23);  // exact 2^-ke
            kacc += ke;
        }

        pbuf[wr][j] = p;
        __syncthreads();
    }

    // logZ = ln2*(kacc + SHIFT*cnt) + log(sum_j p_j * exp(end_j))
    float v = p * __expf(endv[j]);
    float ws = warp_sum(v);
    if ((j & 31) == 0) wred[j >> 5] = ws;
    __syncthreads();
    if (j == 0) {
        float sm = (wred[0] + wred[1]) + (wred[2] + wred[3]);
        g_logz[b] = LN2 * (float)(kacc + SHIFT * cnt) + __logf(sm);
    }
}

// Gold path score: one batch per CTA of 128 threads, strided over t.
__global__ void crf_gold(
    const float* __restrict__ emis,
    const int* __restrict__ tags,
    const int* __restrict__ mask,
    const float* __restrict__ start,
    const float* __restrict__ endv,
    const float* __restrict__ trans)
{
    const int b = blockIdx.x;
    const int tid = threadIdx.x;
    const float* __restrict__ eb = emis + (size_t)b * T_ * K_;
    const int* __restrict__ tg = tags + (size_t)b * T_;
    const int* __restrict__ mb = mask + (size_t)b * T_;

    float sc = 0.0f;
    int cnt = 0;
    for (int t = tid; t < T_; t += 128) {
        int mt = mb[t];
        cnt += mt ? 1 : 0;
        if (t >= 1 && mt && mb[t - 1]) {
            int pr = tg[t - 1]; pr = pr < 0 ? 0 : pr;
            int cr = tg[t];     cr = cr < 0 ? 0 : cr;
            sc += trans[pr * K_ + cr] + eb[(size_t)t * K_ + cr];
        }
    }

    __shared__ float wsc[4];
    __shared__ int wcn[4];
    float s = warp_sum(sc);
    int c = cnt;
    #pragma unroll
    for (int o = 16; o > 0; o >>= 1) c += __shfl_xor_sync(0xffffffffu, c, o);
    if ((tid & 31) == 0) { wsc[tid >> 5] = s; wcn[tid >> 5] = c; }
    __syncthreads();
    if (tid == 0) {
        float total = (wsc[0] + wsc[1]) + (wsc[2] + wsc[3]);
        int ctot = wcn[0] + wcn[1] + wcn[2] + wcn[3];
        int t0 = tg[0];
        float sc0 = (start[t0] + eb[t0]) * (mb[0] ? 1.0f : 0.0f);
        int lenm1 = ctot - 1;
        int last = tg[lenm1];
        g_gold[b] = total + sc0 + endv[last];
    }
}

// Final: mean over batches of (logZ - gold), fixed-order tree reduction.
__global__ void crf_finish(float* __restrict__ out) {
    __shared__ float sm[B_];
    int i = threadIdx.x;
    sm[i] = g_logz[i] - g_gold[i];
    __syncthreads();
    #pragma unroll
    for (int s = 128; s > 0; s >>= 1) {
        if (i < s) sm[i] += sm[i + s];
        __syncthreads();
    }
    if (i == 0) out[0] = sm[0] * (1.0f / B_);
}

extern "C" void kernel_launch(void* const* d_in, const int* in_sizes, int n_in,
                              void* d_out, int out_size) {
    const float* emis   = (const float*)d_in[0];
    const int* tags     = (const int*)d_in[1];
    const int* mask     = (const int*)d_in[2];
    const float* start  = (const float*)d_in[3];
    const float* endv   = (const float*)d_in[4];
    const float* trans  = (const float*)d_in[5];
    float* out = (float*)d_out;

    crf_fwd<<<B_, K_>>>(emis, mask, start, endv, trans);
    crf_gold<<<B_, K_>>>(emis, tags, mask, start, endv, trans);
    crf_finish<<<1, B_>>>(out);
}

// round 6
// speedup vs baseline: 1.6787x; 1.3306x over previous
#include <cuda_runtime.h>

#define B_ 256
#define T_ 1024
#define K_ 128
#define LN2 0.69314718055994531f

__device__ float g_logz[B_];
__device__ float g_gold[B_];

__device__ __forceinline__ void fma2(unsigned long long &acc, unsigned long long a, unsigned long long b) {
    asm("fma.rn.f32x2 %0, %1, %2, %0;" : "+l"(acc) : "l"(a), "l"(b));
}
__device__ __forceinline__ unsigned long long add2(unsigned long long a, unsigned long long b) {
    unsigned long long c;
    asm("add.rn.f32x2 %0, %1, %2;" : "=l"(c) : "l"(a), "l"(b));
    return c;
}
__device__ __forceinline__ unsigned long long pack2(float x, float y) {
    unsigned long long r;
    asm("mov.b64 %0, {%1, %2};" : "=l"(r) : "f"(x), "f"(y));
    return r;
}
__device__ __forceinline__ float2 unpack2(unsigned long long v) {
    float2 f;
    asm("mov.b64 {%0, %1}, %2;" : "=f"(f.x), "=f"(f.y) : "l"(v));
    return f;
}
__device__ __forceinline__ float warp_sum(float v) {
    #pragma unroll
    for (int o = 16; o > 0; o >>= 1) v += __shfl_xor_sync(0xffffffffu, v, o);
    return v;
}

// Forward logZ, exp domain: p_t = (p_{t-1} @ E) * exp(em_t) * 2^-ke, masked,
// where ke = exponent(p_{t-1}[0]) -- read for free from the first GEMV LDS.
// One batch per CTA of 128 threads; thread j owns state j; E column in regs.
// Exactly ONE __syncthreads per step; no warp reductions in the loop.
__global__ __launch_bounds__(128, 2) void crf_fwd(
    const float* __restrict__ emis,   // (B,T,K)
    const int* __restrict__ mask,     // (B,T) int32
    const float* __restrict__ start,  // (K)
    const float* __restrict__ endv,   // (K)
    const float* __restrict__ trans)  // (K,K)
{
    const int b = blockIdx.x;
    const int j = threadIdx.x;
    __shared__ __align__(16) float pb0[K_];
    __shared__ __align__(16) float pb1[K_];
    __shared__ float wred[4];

    // E[:,j] packed over i-pairs
    unsigned long long e2[K_ / 2];
    #pragma unroll
    for (int k = 0; k < K_ / 2; ++k) {
        float ea = __expf(trans[(2 * k) * K_ + j]);
        float ebv = __expf(trans[(2 * k + 1) * K_ + j]);
        e2[k] = pack2(ea, ebv);
    }

    const float* __restrict__ eb = emis + (size_t)b * T_ * K_;
    const int* __restrict__ mb = mask + (size_t)b * T_;

    float p = __expf(start[j] + eb[j]);  // t = 0
    int kacc = 0;
    pb0[j] = p;

    // 3-deep prefetch of exp(em) and mask
    float eA = __expf(eb[1 * K_ + j]);
    float eB = __expf(eb[2 * K_ + j]);
    float eC = __expf(eb[3 * K_ + j]);
    int mA = mb[1], mB = mb[2], mC = mb[3];
    __syncthreads();

#define CRF_STEP(T_IDX, PRD, PWR)                                             \
    {                                                                         \
        const int t_ = (T_IDX);                                               \
        float eem = eA; eA = eB; eB = eC;                                     \
        int mk = mA; mA = mB; mB = mC;                                        \
        if (t_ + 3 < T_) {                                                    \
            eC = __expf(eb[(size_t)(t_ + 3) * K_ + j]);                       \
            mC = mb[t_ + 3];                                                  \
        }                                                                     \
        const ulonglong2* __restrict__ pv = (const ulonglong2*)(PRD);         \
        ulonglong2 q0 = pv[0];                                                \
        /* normalizer from p_prev[0]'s exponent (CTA-uniform) */              \
        float2 f0 = unpack2(q0.x);                                            \
        unsigned int xb = __float_as_uint(f0.x) >> 23;                        \
        int ke = (int)xb - 127;                                               \
        float scale = __uint_as_float((254u - xb) << 23);  /* 2^-ke exact */  \
        if (!mk) { ke = 0; scale = 1.0f; }                                    \
        float eemx = eem * scale;                                             \
        kacc += ke;                                                           \
        unsigned long long a0 = 0ull, a1 = 0ull, a2 = 0ull, a3 = 0ull;        \
        unsigned long long a4 = 0ull, a5 = 0ull, a6 = 0ull, a7 = 0ull;        \
        ulonglong2 q1 = pv[1];                                                \
        ulonglong2 q2 = pv[2];                                                \
        ulonglong2 q3 = pv[3];                                                \
        fma2(a0, q0.x, e2[0]); fma2(a1, q0.y, e2[1]);                         \
        fma2(a2, q1.x, e2[2]); fma2(a3, q1.y, e2[3]);                         \
        fma2(a4, q2.x, e2[4]); fma2(a5, q2.y, e2[5]);                         \
        fma2(a6, q3.x, e2[6]); fma2(a7, q3.y, e2[7]);                         \
        _Pragma("unroll")                                                     \
        for (int k = 1; k < 8; ++k) {                                         \
            ulonglong2 r0 = pv[4 * k];                                        \
            ulonglong2 r1 = pv[4 * k + 1];                                    \
            ulonglong2 r2 = pv[4 * k + 2];                                    \
            ulonglong2 r3 = pv[4 * k + 3];                                    \
            fma2(a0, r0.x, e2[8 * k]);     fma2(a1, r0.y, e2[8 * k + 1]);     \
            fma2(a2, r1.x, e2[8 * k + 2]); fma2(a3, r1.y, e2[8 * k + 3]);     \
            fma2(a4, r2.x, e2[8 * k + 4]); fma2(a5, r2.y, e2[8 * k + 5]);     \
            fma2(a6, r3.x, e2[8 * k + 6]); fma2(a7, r3.y, e2[8 * k + 7]);     \
        }                                                                     \
        a0 = add2(a0, a1); a2 = add2(a2, a3);                                 \
        a4 = add2(a4, a5); a6 = add2(a6, a7);                                 \
        a0 = add2(a0, a2); a4 = add2(a4, a6);                                 \
        a0 = add2(a0, a4);                                                    \
        float2 sp = unpack2(a0);                                              \
        float s = sp.x + sp.y;                                                \
        p = mk ? s * eemx : p;                                                \
        (PWR)[j] = p;                                                         \
        __syncthreads();                                                      \
    }

    // 1023 steps: 511 unrolled pairs + 1 tail
    for (int t = 1; t < T_ - 1; t += 2) {
        CRF_STEP(t,     pb0, pb1)
        CRF_STEP(t + 1, pb1, pb0)
    }
    CRF_STEP(T_ - 1, pb0, pb1)
#undef CRF_STEP

    // logZ = ln2*kacc + log(sum_j p_j * exp(end_j))
    float v = p * __expf(endv[j]);
    float ws = warp_sum(v);
    if ((j & 31) == 0) wred[j >> 5] = ws;
    __syncthreads();
    if (j == 0) {
        float sm = (wred[0] + wred[1]) + (wred[2] + wred[3]);
        g_logz[b] = LN2 * (float)kacc + __logf(sm);
    }
}

// Gold path score: one batch per CTA of 128 threads, strided over t.
__global__ void crf_gold(
    const float* __restrict__ emis,
    const int* __restrict__ tags,
    const int* __restrict__ mask,
    const float* __restrict__ start,
    const float* __restrict__ endv,
    const float* __restrict__ trans)
{
    const int b = blockIdx.x;
    const int tid = threadIdx.x;
    const float* __restrict__ eb = emis + (size_t)b * T_ * K_;
    const int* __restrict__ tg = tags + (size_t)b * T_;
    const int* __restrict__ mb = mask + (size_t)b * T_;

    float sc = 0.0f;
    int cnt = 0;
    for (int t = tid; t < T_; t += 128) {
        int mt = mb[t];
        cnt += mt ? 1 : 0;
        if (t >= 1 && mt && mb[t - 1]) {
            int pr = tg[t - 1]; pr = pr < 0 ? 0 : pr;
            int cr = tg[t];     cr = cr < 0 ? 0 : cr;
            sc += trans[pr * K_ + cr] + eb[(size_t)t * K_ + cr];
        }
    }

    __shared__ float wsc[4];
    __shared__ int wcn[4];
    float s = warp_sum(sc);
    int c = cnt;
    #pragma unroll
    for (int o = 16; o > 0; o >>= 1) c += __shfl_xor_sync(0xffffffffu, c, o);
    if ((tid & 31) == 0) { wsc[tid >> 5] = s; wcn[tid >> 5] = c; }
    __syncthreads();
    if (tid == 0) {
        float total = (wsc[0] + wsc[1]) + (wsc[2] + wsc[3]);
        int ctot = wcn[0] + wcn[1] + wcn[2] + wcn[3];
        int t0 = tg[0];
        float sc0 = (start[t0] + eb[t0]) * (mb[0] ? 1.0f : 0.0f);
        int lenm1 = ctot - 1;
        int last = tg[lenm1];
        g_gold[b] = total + sc0 + endv[last];
    }
}

// Final: mean over batches of (logZ - gold), fixed-order tree reduction.
__global__ void crf_finish(float* __restrict__ out) {
    __shared__ float sm[B_];
    int i = threadIdx.x;
    sm[i] = g_logz[i] - g_gold[i];
    __syncthreads();
    #pragma unroll
    for (int s = 128; s > 0; s >>= 1) {
        if (i < s) sm[i] += sm[i + s];
        __syncthreads();
    }
    if (i == 0) out[0] = sm[0] * (1.0f / B_);
}

extern "C" void kernel_launch(void* const* d_in, const int* in_sizes, int n_in,
                              void* d_out, int out_size) {
    const float* emis   = (const float*)d_in[0];
    const int* tags     = (const int*)d_in[1];
    const int* mask     = (const int*)d_in[2];
    const float* start  = (const float*)d_in[3];
    const float* endv   = (const float*)d_in[4];
    const float* trans  = (const float*)d_in[5];
    float* out = (float*)d_out;

    crf_fwd<<<B_, K_>>>(emis, mask, start, endv, trans);
    crf_gold<<<B_, K_>>>(emis, tags, mask, start, endv, trans);
    crf_finish<<<1, B_>>>(out);
}